// round 17
// baseline (speedup 1.0000x reference)
#include <cuda_runtime.h>
#include <cuda_bf16.h>
#include <mma.h>
#include <math.h>

#define BATCH 512
#define TI    1024
#define DIM   512
#define KEXT  1536          // 3 * DIM (hi | lo | hi)
#define ZSPLIT 6            // split-K over KEXT: chunk 256

// ---------------- scratch (no allocations allowed) ----------------
__device__ float          g_scale[BATCH];
__device__ float          g_b2fac[BATCH];
__device__ float          g_part[ZSPLIT * BATCH * DIM];
__device__ float          g_W1p[(TI + 1) * DIM];       // W1[1+r]+b1 (row TI = b1)
__device__ __nv_bfloat162 g_AextS[BATCH * KEXT / 2];   // [b][1536] hi|lo|hi
__device__ __nv_bfloat162 g_AextN[BATCH * KEXT / 2];   // normed, same layout
__device__ __nv_bfloat162 g_BextW2[KEXT * DIM / 2];    // [1536][512] hi;hi;lo
__device__ __nv_bfloat162 g_BextW3[KEXT * DIM / 2];

// ---------------- packed f32x2 helpers ----------------
typedef unsigned long long u64;

__device__ __forceinline__ u64 fma2(u64 a, u64 b, u64 c) {
    u64 d; asm("fma.rn.f32x2 %0, %1, %2, %3;" : "=l"(d) : "l"(a), "l"(b), "l"(c));
    return d;
}
__device__ __forceinline__ u64 add2(u64 a, u64 b) {
    u64 d; asm("add.rn.f32x2 %0, %1, %2;" : "=l"(d) : "l"(a), "l"(b));
    return d;
}
__device__ __forceinline__ u64 bcast2(float x) {
    u64 d; asm("mov.b64 %0, {%1, %1};" : "=l"(d) : "r"(__float_as_uint(x)));
    return d;
}
__device__ __forceinline__ float2 unpack2(u64 v) {
    unsigned lo, hi;
    asm("mov.b64 {%0, %1}, %2;" : "=r"(lo), "=r"(hi) : "l"(v));
    return make_float2(__uint_as_float(lo), __uint_as_float(hi));
}

union U4 { float4 f; u64 u[2]; };

// hi/lo bf16 split of one float
__device__ __forceinline__ void bfsplit(float v, __nv_bfloat16& h, __nv_bfloat16& l) {
    h = __float2bfloat16_rn(v);
    l = __float2bfloat16_rn(v - __bfloat162float(h));
}

// ============================================================================
// Prep (float4): W1p[r][d] = (r < TI ? W1[1+r][d] : 0) + b1[d]
// ============================================================================
__global__ void __launch_bounds__(128) prep_kernel(
    const float* __restrict__ W1, const float* __restrict__ b1)
{
    const int r = blockIdx.x;
    const int t = threadIdx.x;
    float4 v = ((const float4*)b1)[t];
    if (r < TI) {
        float4 w = ((const float4*)W1)[(size_t)(1 + r) * 128 + t];
        v.x += w.x; v.y += w.y; v.z += w.z; v.w += w.w;
    }
    ((float4*)g_W1p)[(size_t)r * 128 + t] = v;
}

// ============================================================================
// convW: W [512x512] fp32 -> Bext [1536x512] bf16: rows k = hi, 512+k = hi,
// 1024+k = lo. Block per k, 256 threads (2 cols each).
// ============================================================================
__global__ void __launch_bounds__(256) convW_kernel(
    const float* __restrict__ W, __nv_bfloat162* __restrict__ Bext)
{
    const int k = blockIdx.x;
    const int t = threadIdx.x;            // bf162 col 0..255
    float v0 = W[k * DIM + 2 * t];
    float v1 = W[k * DIM + 2 * t + 1];
    __nv_bfloat16 h0, l0, h1, l1;
    bfsplit(v0, h0, l0);
    bfsplit(v1, h1, l1);
    __nv_bfloat162 hp; hp.x = h0; hp.y = h1;
    __nv_bfloat162 lp; lp.x = l0; lp.y = l1;
    Bext[(size_t)k * 256 + t]                  = hp;
    Bext[(size_t)(DIM + k) * 256 + t]          = hp;
    Bext[(size_t)(2 * DIM + k) * 256 + t]      = lp;
}

// ============================================================================
// Stage A (R11 core, FROZEN) + bf16-ext epilogue into g_AextS.
// ============================================================================
__global__ void __launch_bounds__(256) stageA_kernel(
    const float* __restrict__ a,
    const int* __restrict__ mate,
    const int* __restrict__ mask,
    const float* __restrict__ W1)
{
    __shared__ float2 s_ac[TI];
    __shared__ float4 s_sx[2][128];
    __shared__ float4 s_su[2][128];
    __shared__ int    s_wsum[8];
    __shared__ int    s_woff[8];
    __shared__ int    s_n;

    const int b    = blockIdx.x;
    const int tid  = threadIdx.x;
    const int lane = tid & 31;
    const int wid  = tid >> 5;

    const float* arow = a    + (size_t)b * TI;
    const int*   mrow = mate + (size_t)b * TI;
    const int*   krow = mask + (size_t)b * TI;

    const int tb = 4 * tid;
    int mk[4];
    int cnt = 0;
    #pragma unroll
    for (int j = 0; j < 4; j++) { mk[j] = krow[tb + j]; cnt += (mk[j] != 0); }

    int v = cnt;
    #pragma unroll
    for (int o = 1; o < 32; o <<= 1) {
        int n = __shfl_up_sync(0xffffffffu, v, o);
        if (lane >= o) v += n;
    }
    if (lane == 31) s_wsum[wid] = v;
    __syncthreads();
    if (tid == 0) {
        int run = 0;
        #pragma unroll
        for (int k = 0; k < 8; k++) { s_woff[k] = run; run += s_wsum[k]; }
        s_n = run;
    }
    __syncthreads();

    int pos = s_woff[wid] + (v - cnt);
    #pragma unroll
    for (int j = 0; j < 4; j++) {
        if (mk[j] != 0) {
            int mt  = mrow[tb + j];
            int row = (mt >= 0) ? mt : TI;
            s_ac[pos] = make_float2(arow[tb + j], __int_as_float(row));
            pos++;
        }
    }
    __syncthreads();
    const int nact = s_n;

    const int half = tid >> 7;
    const int c    = tid & 127;
    const int mid  = nact >> 1;
    const int i0   = half ? mid : 0;
    const int i1   = half ? nact : mid;

    U4 w10; w10.f = __ldg((const float4*)W1 + c);
    const float4* Wp = (const float4*)g_W1p;

    u64 sx0 = 0ull, sx1 = 0ull;
    u64 su0 = 0ull, su1 = 0ull;

    int i = i0;
    const int i1u = i0 + ((i1 - i0) & ~3);
    for (; i < i1u; i += 4) {
        float2 ac[4];
        #pragma unroll
        for (int u = 0; u < 4; u++) ac[u] = s_ac[i + u];
        U4 w[4];
        #pragma unroll
        for (int u = 0; u < 4; u++)
            w[u].f = __ldg(&Wp[(size_t)__float_as_int(ac[u].y) * 128 + c]);
        #pragma unroll
        for (int u = 0; u < 4; u++) {
            u64 av2 = bcast2(ac[u].x);
            u64 x0 = fma2(av2, w10.u[0], w[u].u[0]);
            u64 x1 = fma2(av2, w10.u[1], w[u].u[1]);
            sx0 = add2(sx0, x0);
            sx1 = add2(sx1, x1);
            su0 = fma2(x0, x0, su0);
            su1 = fma2(x1, x1, su1);
        }
    }
    for (; i < i1; i++) {
        float2 ac = s_ac[i];
        U4 w; w.f = __ldg(&Wp[(size_t)__float_as_int(ac.y) * 128 + c]);
        u64 av2 = bcast2(ac.x);
        u64 x0 = fma2(av2, w10.u[0], w.u[0]);
        u64 x1 = fma2(av2, w10.u[1], w.u[1]);
        sx0 = add2(sx0, x0);
        sx1 = add2(sx1, x1);
        su0 = fma2(x0, x0, su0);
        su1 = fma2(x1, x1, su1);
    }

    {
        float2 a0 = unpack2(sx0), a1 = unpack2(sx1);
        s_sx[half][c] = make_float4(a0.x, a0.y, a1.x, a1.y);
        float2 b0 = unpack2(su0), b1v = unpack2(su1);
        s_su[half][c] = make_float4(b0.x, b0.y, b1v.x, b1v.y);
    }
    __syncthreads();

    if (tid < 128) {
        const float q0 = 0.3989422804014327f;
        float4 X0 = s_sx[0][tid], X1 = s_sx[1][tid];
        float4 U0 = s_su[0][tid], U1 = s_su[1][tid];
        float o[4];
        o[0] = fmaf(0.5f, X0.x + X1.x, q0 * (U0.x + U1.x));
        o[1] = fmaf(0.5f, X0.y + X1.y, q0 * (U0.y + U1.y));
        o[2] = fmaf(0.5f, X0.z + X1.z, q0 * (U0.z + U1.z));
        o[3] = fmaf(0.5f, X0.w + X1.w, q0 * (U0.w + U1.w));

        // hi/lo bf16-ext write: row b, cols 4t..4t+3
        __nv_bfloat16 h[4], l[4];
        #pragma unroll
        for (int j = 0; j < 4; j++) bfsplit(o[j], h[j], l[j]);
        __nv_bfloat162 hp0; hp0.x = h[0]; hp0.y = h[1];
        __nv_bfloat162 hp1; hp1.x = h[2]; hp1.y = h[3];
        __nv_bfloat162 lp0; lp0.x = l[0]; lp0.y = l[1];
        __nv_bfloat162 lp1; lp1.x = l[2]; lp1.y = l[3];
        const size_t base = (size_t)b * 768;           // 1536/2
        const int t2 = 2 * tid;
        g_AextS[base + t2]           = hp0;
        g_AextS[base + t2 + 1]       = hp1;
        g_AextS[base + 256 + t2]     = lp0;
        g_AextS[base + 256 + t2 + 1] = lp1;
        g_AextS[base + 512 + t2]     = hp0;
        g_AextS[base + 512 + t2 + 1] = hp1;
    }
    if (tid == 0) {
        g_scale[b] = 1.0f / fmaxf((float)nact, 1.0f);
        g_b2fac[b] = (nact > 0) ? 1.0f : 0.0f;
    }
}

// ============================================================================
// bf16 WMMA GEMM, split-K: C[512,512] = Aext[512,1536] @ Bext[1536,512].
// BM=BN=64, BK=32. grid (8,8,ZSPLIT)=384 blocks, 256 thr = 8 warps (4m x 2n),
// warp tile 16x32 = two 16x16x16 bf16 mma, fp32 accum -> g_part slice.
// ============================================================================
__global__ void __launch_bounds__(256) gemm_wmma_kernel(
    const __nv_bfloat162* __restrict__ Aext2,
    const __nv_bfloat162* __restrict__ Bext2)
{
    using namespace nvcuda::wmma;
    __shared__ __nv_bfloat16 As[64][32];   // [m][k]
    __shared__ __nv_bfloat16 Bs[32][64];   // [k][n]

    const __nv_bfloat16* Aext = (const __nv_bfloat16*)Aext2;
    const __nv_bfloat16* Bext = (const __nv_bfloat16*)Bext2;
    float* P = g_part + (size_t)blockIdx.z * DIM * DIM;

    const int row0 = blockIdx.y * 64;
    const int col0 = blockIdx.x * 64;
    const int kbeg = blockIdx.z * (KEXT / ZSPLIT);   // 256
    const int tid  = threadIdx.x;
    const int warp = tid >> 5;
    const int wm   = warp >> 1;        // 0..3 -> m offset 16*wm
    const int wn   = warp & 1;         // 0..1 -> n offset 32*wn

    fragment<accumulator, 16, 16, 16, float> acc0, acc1;
    fill_fragment(acc0, 0.0f);
    fill_fragment(acc1, 0.0f);
    fragment<matrix_a, 16, 16, 16, __nv_bfloat16, row_major> fa;
    fragment<matrix_b, 16, 16, 16, __nv_bfloat16, row_major> fb;

    // per-thread load coords (uint4 = 8 bf16)
    const int aidx = tid * 8;
    const int arr_ = aidx >> 5, ac_ = aidx & 31;     // A: 64x32
    const int brr_ = aidx >> 6, bc_ = aidx & 63;     // B: 32x64

    for (int step = 0; step < (KEXT / ZSPLIT) / 32; step++) {   // 8 steps
        const int k0 = kbeg + step * 32;
        *(uint4*)&As[arr_][ac_] =
            *(const uint4*)&Aext[(size_t)(row0 + arr_) * KEXT + k0 + ac_];
        *(uint4*)&Bs[brr_][bc_] =
            *(const uint4*)&Bext[(size_t)(k0 + brr_) * DIM + col0 + bc_];
        __syncthreads();

        #pragma unroll
        for (int kk = 0; kk < 32; kk += 16) {
            load_matrix_sync(fa, &As[wm * 16][kk], 32);
            load_matrix_sync(fb, &Bs[kk][wn * 32], 64);
            mma_sync(acc0, fa, fb, acc0);
            load_matrix_sync(fb, &Bs[kk][wn * 32 + 16], 64);
            mma_sync(acc1, fa, fb, acc1);
        }
        __syncthreads();
    }

    store_matrix_sync(&P[(size_t)(row0 + wm * 16) * DIM + col0 + wn * 32],
                      acc0, DIM, mem_row_major);
    store_matrix_sync(&P[(size_t)(row0 + wm * 16) * DIM + col0 + wn * 32 + 16],
                      acc1, DIM, mem_row_major);
}

// ============================================================================
// Combine mode-0 partials + scale/bias + LayerNorm -> g_AextN (bf16 hi/lo).
// 512 threads = 4 independent 128-thread row-teams; grid = BATCH/4.
// ============================================================================
__global__ void __launch_bounds__(512) combine0_ln_kernel(
    const float* __restrict__ b2,
    const float* __restrict__ ln_g,
    const float* __restrict__ ln_b)
{
    const int tid = threadIdx.x;
    const int g   = tid >> 7;
    const int t   = tid & 127;
    const int b   = blockIdx.x * 4 + g;
    const int lane = t & 31, wid = t >> 5;

    __shared__ float red[4][4];
    __shared__ float s_mu[4], s_rstd[4];

    const float4* P = (const float4*)g_part;
    const int idx = b * 128 + t;

    float4 v = P[idx];
    #pragma unroll
    for (int s = 1; s < ZSPLIT; s++) {
        float4 p = P[s * (BATCH * 128) + idx];
        v.x += p.x; v.y += p.y; v.z += p.z; v.w += p.w;
    }

    const float sc = g_scale[b];
    const float bf = g_b2fac[b];
    const float4 b2v = ((const float4*)b2)[t];
    float4 x;
    x.x = fmaf(v.x, sc, b2v.x * bf);
    x.y = fmaf(v.y, sc, b2v.y * bf);
    x.z = fmaf(v.z, sc, b2v.z * bf);
    x.w = fmaf(v.w, sc, b2v.w * bf);

    float s = (x.x + x.y) + (x.z + x.w);
    #pragma unroll
    for (int o = 16; o; o >>= 1) s += __shfl_xor_sync(0xffffffffu, s, o);
    if (lane == 0) red[g][wid] = s;
    __syncthreads();
    if (t == 0)
        s_mu[g] = (red[g][0] + red[g][1] + red[g][2] + red[g][3]) * (1.0f / (float)DIM);
    __syncthreads();
    const float mu = s_mu[g];
    float4 dx = make_float4(x.x - mu, x.y - mu, x.z - mu, x.w - mu);

    s = (dx.x * dx.x + dx.y * dx.y) + (dx.z * dx.z + dx.w * dx.w);
    #pragma unroll
    for (int o = 16; o; o >>= 1) s += __shfl_xor_sync(0xffffffffu, s, o);
    if (lane == 0) red[g][wid] = s;
    __syncthreads();
    if (t == 0)
        s_rstd[g] = rsqrtf((red[g][0] + red[g][1] + red[g][2] + red[g][3])
                           * (1.0f / (float)DIM) + 1e-5f);
    __syncthreads();
    const float rstd = s_rstd[g];

    const float4 gv = ((const float4*)ln_g)[t];
    const float4 bv = ((const float4*)ln_b)[t];
    float o[4];
    o[0] = fmaf(dx.x * rstd, gv.x, bv.x);
    o[1] = fmaf(dx.y * rstd, gv.y, bv.y);
    o[2] = fmaf(dx.z * rstd, gv.z, bv.z);
    o[3] = fmaf(dx.w * rstd, gv.w, bv.w);

    __nv_bfloat16 h[4], l[4];
    #pragma unroll
    for (int j = 0; j < 4; j++) bfsplit(o[j], h[j], l[j]);
    __nv_bfloat162 hp0; hp0.x = h[0]; hp0.y = h[1];
    __nv_bfloat162 hp1; hp1.x = h[2]; hp1.y = h[3];
    __nv_bfloat162 lp0; lp0.x = l[0]; lp0.y = l[1];
    __nv_bfloat162 lp1; lp1.x = l[2]; lp1.y = l[3];
    const size_t base = (size_t)b * 768;
    const int t2 = 2 * t;
    g_AextN[base + t2]           = hp0;
    g_AextN[base + t2 + 1]       = hp1;
    g_AextN[base + 256 + t2]     = lp0;
    g_AextN[base + 256 + t2 + 1] = lp1;
    g_AextN[base + 512 + t2]     = hp0;
    g_AextN[base + 512 + t2 + 1] = hp1;
}

// ============================================================================
// Combine mode-1 partials + bias -> out (float4).
// ============================================================================
__global__ void __launch_bounds__(256) combine1_kernel(
    const float* __restrict__ b3,
    float* __restrict__ out)
{
    const int idx = blockIdx.x * 256 + threadIdx.x;
    const int col = idx & 127;
    const float4* P = (const float4*)g_part;

    float4 v = ((const float4*)b3)[col];
    #pragma unroll
    for (int s = 0; s < ZSPLIT; s++) {
        float4 p = P[s * (BATCH * 128) + idx];
        v.x += p.x; v.y += p.y; v.z += p.z; v.w += p.w;
    }
    ((float4*)out)[idx] = v;
}

// ============================================================================
// launch
// ============================================================================
extern "C" void kernel_launch(void* const* d_in, const int* in_sizes, int n_in,
                              void* d_out, int out_size)
{
    const float* a    = (const float*)d_in[0];
    const int*   mate = (const int*)d_in[1];
    const int*   mask = (const int*)d_in[2];
    const float* W1   = (const float*)d_in[3];
    const float* b1   = (const float*)d_in[4];
    const float* W2   = (const float*)d_in[5];
    const float* b2   = (const float*)d_in[6];
    const float* ln_g = (const float*)d_in[7];
    const float* ln_b = (const float*)d_in[8];
    const float* W3   = (const float*)d_in[9];
    const float* b3   = (const float*)d_in[10];
    float* out = (float*)d_out;

    (void)in_sizes; (void)n_in; (void)out_size;

    __nv_bfloat162 *dAS, *dAN, *dBW2, *dBW3;
    cudaGetSymbolAddress((void**)&dAS,  g_AextS);
    cudaGetSymbolAddress((void**)&dAN,  g_AextN);
    cudaGetSymbolAddress((void**)&dBW2, g_BextW2);
    cudaGetSymbolAddress((void**)&dBW3, g_BextW3);

    prep_kernel<<<TI + 1, 128>>>(W1, b1);
    convW_kernel<<<DIM, 256>>>(W2, dBW2);
    convW_kernel<<<DIM, 256>>>(W3, dBW3);
    stageA_kernel<<<BATCH, 256>>>(a, mate, mask, W1);
    gemm_wmma_kernel<<<dim3(8, 8, ZSPLIT), 256>>>(dAS, dBW2);
    combine0_ln_kernel<<<BATCH / 4, 512>>>(b2, ln_g, ln_b);
    gemm_wmma_kernel<<<dim3(8, 8, ZSPLIT), 256>>>(dAN, dBW3);
    combine1_kernel<<<BATCH * DIM / 4 / 256, 256>>>(b3, out);
}